// round 11
// baseline (speedup 1.0000x reference)
#include <cuda_runtime.h>
#include <cuda_bf16.h>
#include <math.h>

#define H      1024
#define H2     2048
#define NB     16
#define BEAM   3
#define DEPTH  5
#define MAXN   376            // 1 + 25*5*3
#define BPLEN  8
#define EPSLN  1e-5f
#define UCBC   1.414f
#define NEGINF (-INFINITY)
#define NBLK   296            // 2 CTAs per SM on 148 SMs; whole grid co-resident

// ---------------- persistent device state (no allocs allowed) ----------------
__device__ float g_emb[NB * MAXN * H];        // tree embeddings (~24.6 MB)
__device__ float g_vals[NB * MAXN];
__device__ int   g_visits[NB * MAXN];
__device__ int   g_n[NB];
__device__ int   g_cur[NB];
__device__ int   g_expand[NB];
__device__ float g_X[NB * H];                 // staged cur_emb
__device__ float g_h[NB * BEAM * H2];         // G1 output
__device__ float g_ne[NB * BEAM * H];         // G2 output (candidate children)
__device__ float g_zp[4 * NB * H];            // root GEMM k-split partials
__device__ float g_bestv[NB];
__device__ unsigned int g_bar_cnt;            // zero-init; returns to 0 after each barrier
__device__ unsigned int g_bar_gen;            // monotonically increasing across replays

// ---------------- helpers ----------------
__device__ __forceinline__ float geluf(float x) {
    return 0.5f * x * (1.0f + erff(x * 0.70710678118654752440f));
}
__device__ __forceinline__ float warp_sum(float v) {
    v += __shfl_xor_sync(0xffffffffu, v, 16);
    v += __shfl_xor_sync(0xffffffffu, v, 8);
    v += __shfl_xor_sync(0xffffffffu, v, 4);
    v += __shfl_xor_sync(0xffffffffu, v, 2);
    v += __shfl_xor_sync(0xffffffffu, v, 1);
    return v;
}

// Software grid barrier. Safe because all NBLK blocks are co-resident.
__device__ __forceinline__ void grid_barrier() {
    __threadfence();
    __syncthreads();
    if (threadIdx.x == 0) {
        unsigned int gen = ((volatile unsigned int*)&g_bar_gen)[0];
        unsigned int t = atomicAdd(&g_bar_cnt, 1u);
        if (t == NBLK - 1) {
            atomicExch(&g_bar_cnt, 0u);
            __threadfence();
            atomicExch(&g_bar_gen, gen + 1u);
        } else {
            while (((volatile unsigned int*)&g_bar_gen)[0] == gen) { __nanosleep(32); }
            __threadfence();
        }
    }
    __syncthreads();
}

// ---------------- root: z_partial[kc][b][j] = sum_{k in slice} x[b][k]*Wte[k][j]
__global__ void root1_kernel(const float* __restrict__ p, const float* __restrict__ c,
                             const float* __restrict__ Wte) {
    __shared__ float xs[8 * 512];
    int tid = threadIdx.x;
    int jb = blockIdx.x;      // 0..3
    int bg = blockIdx.y;      // 0..1
    int kc = blockIdx.z;      // 0..3
    for (int i = tid; i < 8 * 512; i += 256) {
        int bl = i >> 9, kk = i & 511;
        int k = kc * 512 + kk;
        int bb = bg * 8 + bl;
        xs[i] = (k < H) ? p[bb * H + k] : c[bb * H + (k - H)];
    }
    __syncthreads();
    int j = jb * 256 + tid;
    float acc[8] = {0.f, 0.f, 0.f, 0.f, 0.f, 0.f, 0.f, 0.f};
    for (int kk = 0; kk < 512; kk++) {
        float w = Wte[(kc * 512 + kk) * H + j];
#pragma unroll
        for (int bl = 0; bl < 8; bl++) acc[bl] += xs[bl * 512 + kk] * w;
    }
#pragma unroll
    for (int bl = 0; bl < 8; bl++) {
        int bb = bg * 8 + bl;
        g_zp[(kc * NB + bb) * H + j] = acc[bl];
    }
}

// ---------------- root: bias+gelu+layernorm, init tree ----------------
__global__ void root2_kernel(const float* __restrict__ bte, const float* __restrict__ gln,
                             const float* __restrict__ bln, const float* __restrict__ wv,
                             const float* __restrict__ bv) {
    int b = blockIdx.x, tid = threadIdx.x;
    int lane = tid & 31, warp = tid >> 5;
    __shared__ float red[8];
    float zv[4];
    float s = 0.f;
#pragma unroll
    for (int q = 0; q < 4; q++) {
        int j = tid + q * 256;
        float z = g_zp[(0 * NB + b) * H + j] + g_zp[(1 * NB + b) * H + j] +
                  g_zp[(2 * NB + b) * H + j] + g_zp[(3 * NB + b) * H + j] + bte[j];
        z = geluf(z);
        zv[q] = z;
        s += z;
    }
    s = warp_sum(s);
    if (lane == 0) red[warp] = s;
    __syncthreads();
    if (tid == 0) {
        float t = 0.f;
#pragma unroll
        for (int w = 0; w < 8; w++) t += red[w];
        red[0] = t;
    }
    __syncthreads();
    float mu = red[0] * (1.0f / H);
    __syncthreads();
    float s2 = 0.f;
#pragma unroll
    for (int q = 0; q < 4; q++) { float d = zv[q] - mu; s2 += d * d; }
    s2 = warp_sum(s2);
    if (lane == 0) red[warp] = s2;
    __syncthreads();
    if (tid == 0) {
        float t = 0.f;
#pragma unroll
        for (int w = 0; w < 8; w++) t += red[w];
        red[0] = t;
    }
    __syncthreads();
    float var = red[0] * (1.0f / H);
    float inv = 1.0f / sqrtf(var + EPSLN);
    __syncthreads();
    float vp = 0.f;
#pragma unroll
    for (int q = 0; q < 4; q++) {
        int j = tid + q * 256;
        float r = gln[j] * (zv[q] - mu) * inv + bln[j];
        g_emb[(b * MAXN + 0) * H + j] = r;
        vp += r * wv[j];
    }
    vp = warp_sum(vp);
    if (lane == 0) red[warp] = vp;
    __syncthreads();
    if (tid == 0) {
        float t = 0.f;
#pragma unroll
        for (int w = 0; w < 8; w++) t += red[w];
        g_vals[b * MAXN + 0] = t + bv[0];
        g_visits[b * MAXN + 0] = 1;
        g_n[b] = 1;
        g_cur[b] = 0;
    }
}

// ---------------- prep for sim0/depth0 ----------------
__global__ void prep_kernel() {
    int b = blockIdx.x, tid = threadIdx.x;
    if (tid == 0) {
        g_cur[b] = 0;
        g_expand[b] = ((g_n[b] - 1) < BEAM) ? 1 : 0;
    }
    __syncthreads();
    for (int k = tid; k < H; k += 128)
        g_X[b * H + k] = g_emb[(b * MAXN + 0) * H + k];
}

// ---------------- G1 phase (templated on active batch slots) ----------------
// h[act[j]][r] = gelu(dot(W1row[r], X[act[j]]) + b1[r]); tile = warp*296 + bid.
template<int NBAT>
__device__ __forceinline__ void g1_phase(float4* sx4, const int* s_act, int na,
                                         const float* __restrict__ W1,
                                         const float* __restrict__ b1) {
    int tid = threadIdx.x;
    const float4* X4 = (const float4*)g_X;
    for (int i = tid; i < NBAT * 256; i += 256) {
        int j = i >> 8, k4 = i & 255;
        int bb = s_act[j < na ? j : 0];
        sx4[j * 256 + k4] = X4[bb * 256 + k4];
    }
    __syncthreads();

    int warp = tid >> 5, lane = tid & 31;
    int tt = warp * NBLK + blockIdx.x;
    if (tt < 1536) {
        int row0 = tt * 4;
        float acc[NBAT][4];
#pragma unroll
        for (int b = 0; b < NBAT; b++)
#pragma unroll
            for (int i = 0; i < 4; i++) acc[b][i] = 0.f;

        const float4* W4 = (const float4*)W1;
        const float4* wp = W4 + (size_t)row0 * 256 + lane;
#pragma unroll 2
        for (int t = 0; t < 8; t++) {
            float4 wr[4];
#pragma unroll
            for (int i = 0; i < 4; i++) wr[i] = wp[t * 32 + i * 256];
            int k4 = t * 32 + lane;
#pragma unroll
            for (int b = 0; b < NBAT; b++) {
                float4 x = sx4[b * 256 + k4];
#pragma unroll
                for (int i = 0; i < 4; i++) {
                    acc[b][i] = fmaf(wr[i].x, x.x, acc[b][i]);
                    acc[b][i] = fmaf(wr[i].y, x.y, acc[b][i]);
                    acc[b][i] = fmaf(wr[i].z, x.z, acc[b][i]);
                    acc[b][i] = fmaf(wr[i].w, x.w, acc[b][i]);
                }
            }
        }
        const int NQ = (NBAT * 4 + 31) / 32;
        float red[NQ];
#pragma unroll
        for (int q = 0; q < NQ; q++) red[q] = 0.f;
#pragma unroll
        for (int m = 0; m < NBAT * 4; m++) {
            float v = warp_sum(acc[m >> 2][m & 3]);
            if (lane == (m & 31)) red[m >> 5] = v;
        }
#pragma unroll
        for (int q = 0; q < NQ; q++) {
            int m = q * 32 + lane;
            if (m < NBAT * 4) {
                int j = m >> 2;
                if (j < na) {
                    int r = row0 + (m & 3);
                    g_h[s_act[j] * (BEAM * H2) + r] = geluf(red[q] + b1[r]);
                }
            }
        }
    }
}

// ---------------- G2 phase (templated on group size) ----------------
// ne[act[j]][r] = X[act[j]][d] + 0.1*(dot(W2row[r], h[act[j]][w]) + b2[r]), r=w*1024+d
// bid = ib + 49*(w + 3*bg); group bg covers act slots [bg*8, bg*8+GB).
template<int GB>
__device__ __forceinline__ void g2_phase(float4* sh4, const int* s_act, int na,
                                         const float* __restrict__ W2,
                                         const float* __restrict__ b2) {
    int tid = threadIdx.x, bid = blockIdx.x;
    if (bid >= 294) return;
    int ib  = bid % 49;
    int rem = bid / 49;
    int w   = rem % 3;
    int bg  = rem / 3;
    if (bg * 8 >= na) return;     // whole group empty (block-uniform)

    const float4* Hh4 = (const float4*)g_h;
    for (int i = tid; i < GB * 512; i += 256) {
        int bl = i >> 9, k4 = i & 511;
        int j = bg * 8 + bl;
        int bb = s_act[j < na ? j : 0];
        sh4[bl * 512 + k4] = Hh4[bb * (BEAM * H2 / 4) + w * 512 + k4];
    }
    __syncthreads();

    int warp = tid >> 5, lane = tid & 31;
    int tile = warp * 49 + ib;
    if (tile < 256) {
        int row0 = w * 1024 + tile * 4;
        float acc[GB][4];
#pragma unroll
        for (int b = 0; b < GB; b++)
#pragma unroll
            for (int i = 0; i < 4; i++) acc[b][i] = 0.f;

        const float4* W4 = (const float4*)W2;
        const float4* wp = W4 + (size_t)row0 * 512 + lane;
#pragma unroll 2
        for (int t = 0; t < 16; t++) {
            float4 wr[4];
#pragma unroll
            for (int i = 0; i < 4; i++) wr[i] = wp[t * 32 + i * 512];
            int k4 = t * 32 + lane;
#pragma unroll
            for (int b = 0; b < GB; b++) {
                float4 x = sh4[b * 512 + k4];
#pragma unroll
                for (int i = 0; i < 4; i++) {
                    acc[b][i] = fmaf(wr[i].x, x.x, acc[b][i]);
                    acc[b][i] = fmaf(wr[i].y, x.y, acc[b][i]);
                    acc[b][i] = fmaf(wr[i].z, x.z, acc[b][i]);
                    acc[b][i] = fmaf(wr[i].w, x.w, acc[b][i]);
                }
            }
        }
        float red = 0.f;
#pragma unroll
        for (int m = 0; m < GB * 4; m++) {
            float v = warp_sum(acc[m >> 2][m & 3]);
            if (lane == m) red = v;
        }
        int m = lane;
        if (m < GB * 4) {
            int j = bg * 8 + (m >> 2);
            if (j < na) {
                int bb = s_act[j];
                int r2 = row0 + (m & 3);
                float nv = g_X[bb * H + (r2 & 1023)] + 0.1f * (red + b2[r2]);
                g_ne[bb * (BEAM * H) + r2] = nv;
            }
        }
    }
}

// ---------------- ctl phase (block b, 256 threads): finalize (sim,d) + prep next ----
__device__ void ctl_phase(int b, int sim, int d, int ns,
                          const float* __restrict__ wv, const float* __restrict__ bv) {
    int tid = threadIdx.x, lane = tid & 31, warp = tid >> 5;
    __shared__ float sv[BEAM];
    __shared__ int st[4];
    if (tid == 0) { st[0] = g_n[b]; st[1] = g_cur[b]; st[2] = g_expand[b]; }
    __syncthreads();
    int n = st[0], cur = st[1], exp = st[2];

    if (exp) {
        if (warp < BEAM) {
            float s = 0.f;
            for (int k = lane; k < H; k += 32)
                s += g_ne[b * (BEAM * H) + warp * H + k] * wv[k];
            s = warp_sum(s);
            if (lane == 0) sv[warp] = s + bv[0];
        }
        __syncthreads();
#pragma unroll
        for (int w = 0; w < BEAM; w++) {
            int idx = n + w;
            if (idx < MAXN) {
                for (int k = tid; k < H; k += 256)
                    g_emb[(b * MAXN + idx) * H + k] = g_ne[b * (BEAM * H) + w * H + k];
            }
        }
        if (tid == 0) {
#pragma unroll
            for (int w = 0; w < BEAM; w++) {
                int idx = n + w;
                if (idx < MAXN) {
                    g_vals[b * MAXN + idx] = sv[w];
                    g_visits[b * MAXN + idx] = 1;
                }
            }
        }
        n += BEAM;
    }
    __syncthreads();
    if (tid == 0) {
        g_n[b] = n;
        if (d < DEPTH - 1) {
            // UCB selection (exact reference semantics incl. heap-index quirk)
            int pv = 0;
#pragma unroll
            for (int i = 0; i < BEAM; i++) {
                int pi = cur * BEAM + i;
                if (pi < n) pv += g_visits[b * MAXN + (pi < MAXN - 1 ? pi : MAXN - 1)];
            }
            float log_pv = logf((float)(pv > 1 ? pv : 1));
            float best = NEGINF; int bi = cur;
#pragma unroll
            for (int ci = 0; ci < BEAM; ci++) {
                int child = cur * BEAM + 1 + ci;
                int safe = child < MAXN - 1 ? child : MAXN - 1;
                int vis = g_visits[b * MAXN + safe];
                float cn = (float)(vis > 1 ? vis : 1);
                float ucb = g_vals[b * MAXN + safe] + UCBC * sqrtf(log_pv / cn);
                if (child >= n) ucb = NEGINF;
                if (ucb > best) { best = ucb; bi = child; }
            }
            g_cur[b] = bi;
        } else {
            // leaf + backprop
            int leaf = cur < n - 1 ? cur : n - 1;
            float lv = g_vals[b * MAXN + leaf];
            int node = leaf;
#pragma unroll
            for (int it = 0; it < BPLEN; it++) {
                if (node > 0) {
                    int pnode = (node - 1) / BEAM;
                    float pc = (float)g_visits[b * MAXN + pnode];
                    g_vals[b * MAXN + pnode] =
                        (g_vals[b * MAXN + pnode] * pc + lv) / (pc + 1.0f);
                    g_visits[b * MAXN + pnode] += 1;
                    node = pnode;
                }
            }
            g_visits[b * MAXN + leaf] += 1;
        }
    }
    __syncthreads();

    // prep next step
    int sim_p = (d < DEPTH - 1) ? sim : sim + 1;
    int d_p   = (d < DEPTH - 1) ? d + 1 : 0;
    if (sim_p >= ns) {
        if (tid == 0) g_expand[b] = 0;
    } else {
        if (tid == 0) {
            int cp = (d_p == 0) ? 0 : g_cur[b];
            g_cur[b] = cp;
            int np = g_n[b];
            g_expand[b] = ((np - 1) < (cp + 1) * BEAM) ? 1 : 0;
            st[3] = cp;
        }
        __syncthreads();
        int cp = st[3];
        for (int k = tid; k < H; k += 256)
            g_X[b * H + k] = g_emb[(b * MAXN + cp) * H + k];
    }
}

// ---------------- persistent main loop: 125 steps, grid barriers between phases ----
__global__ void __launch_bounds__(256, 2)
main_kernel(const float* __restrict__ W1, const float* __restrict__ b1,
            const float* __restrict__ W2, const float* __restrict__ b2,
            const float* __restrict__ wv, const float* __restrict__ bv,
            const int* __restrict__ nsp) {
    extern __shared__ float4 smem4[];   // 64KB, reused by g1 (X slab) and g2 (h slab)
    __shared__ int s_act[NB];
    __shared__ int s_nact;
    int tid = threadIdx.x;
    int bid = blockIdx.x;
    int ns = nsp[0];

    for (int sim = 0; sim < ns; sim++) {
        for (int d = 0; d < DEPTH; d++) {
            // Deterministic per-batch compaction; g_expand was written before the
            // preceding barrier, so every block computes the identical list.
            if (tid < 32) {
                int e = (tid < NB) ? g_expand[tid] : 0;
                unsigned mask = __ballot_sync(0xffffffffu, e != 0);
                if (tid == 0) s_nact = __popc(mask);
                if (tid < NB && e)
                    s_act[__popc(mask & ((1u << tid) - 1u))] = tid;
            }
            __syncthreads();
            int na = s_nact;
            __syncthreads();

            if (na > 0) {
                if (na > 8)      g1_phase<16>(smem4, s_act, na, W1, b1);
                else if (na > 4) g1_phase<8>(smem4, s_act, na, W1, b1);
                else             g1_phase<4>(smem4, s_act, na, W1, b1);
                grid_barrier();
                if (na > 4)      g2_phase<8>(smem4, s_act, na, W2, b2);
                else             g2_phase<4>(smem4, s_act, na, W2, b2);
                grid_barrier();
            }
            if (bid < NB) ctl_phase(bid, sim, d, ns, wv, bv);
            grid_barrier();
        }
    }
}

// ---------------- final: per-batch argmax (first-max) + copy emb ----------------
__global__ void final1_kernel(float* __restrict__ out) {
    int b = blockIdx.x, tid = threadIdx.x;
    int lane = tid & 31, warp = tid >> 5;
    __shared__ float wmax[8];
    __shared__ int s_bi;
    int n = g_n[b];
    float mx = NEGINF;
    for (int i = tid; i < n; i += 256) mx = fmaxf(mx, g_vals[b * MAXN + i]);
#pragma unroll
    for (int off = 16; off > 0; off >>= 1)
        mx = fmaxf(mx, __shfl_xor_sync(0xffffffffu, mx, off));
    if (lane == 0) wmax[warp] = mx;
    __syncthreads();
    if (tid == 0) {
        float m = wmax[0];
#pragma unroll
        for (int w = 1; w < 8; w++) m = fmaxf(m, wmax[w]);
        wmax[0] = m;
        s_bi = 0x7fffffff;
    }
    __syncthreads();
    float M = wmax[0];
    for (int i = tid; i < n; i += 256)
        if (g_vals[b * MAXN + i] == M) atomicMin(&s_bi, i);
    __syncthreads();
    int bi = s_bi;
    for (int k = tid; k < H; k += 256)
        out[b * H + k] = g_emb[(b * MAXN + bi) * H + k];
    if (tid == 0) g_bestv[b] = M;
}

__global__ void final2_kernel(float* __restrict__ out) {
    int lane = threadIdx.x;
    float v = (lane < NB) ? g_bestv[lane] : NEGINF;
    float m = v;
#pragma unroll
    for (int off = 16; off > 0; off >>= 1)
        m = fmaxf(m, __shfl_xor_sync(0xffffffffu, m, off));
    if (lane < NB) {
        float conf = fminf(v / (m + 1e-8f), 1.0f);
        out[NB * H + lane] = conf;          // confidence [16]
        out[NB * H + NB + lane] = v;        // best_vals  [16]
    }
}

// ---------------- launch ----------------
extern "C" void kernel_launch(void* const* d_in, const int* in_sizes, int n_in,
                              void* d_out, int out_size) {
    const float* p   = (const float*)d_in[0];
    const float* c   = (const float*)d_in[1];
    const float* Wte = (const float*)d_in[2];
    const float* bte = (const float*)d_in[3];
    const float* gln = (const float*)d_in[4];
    const float* bln = (const float*)d_in[5];
    const float* wv  = (const float*)d_in[6];
    const float* bv  = (const float*)d_in[7];
    const float* W1  = (const float*)d_in[8];
    const float* b1  = (const float*)d_in[9];
    const float* W2  = (const float*)d_in[10];
    const float* b2  = (const float*)d_in[11];
    const int*   nsp = (const int*)d_in[12];
    float* out = (float*)d_out;

    cudaFuncSetAttribute(main_kernel, cudaFuncAttributeMaxDynamicSharedMemorySize, 65536);

    root1_kernel<<<dim3(4, 2, 4), 256>>>(p, c, Wte);
    root2_kernel<<<NB, 256>>>(bte, gln, bln, wv, bv);
    prep_kernel<<<NB, 128>>>();
    main_kernel<<<NBLK, 256, 65536>>>(W1, b1, W2, b2, wv, bv, nsp);
    final1_kernel<<<NB, 256>>>(out);
    final2_kernel<<<1, 32>>>(out);
}

// round 12
// speedup vs baseline: 1.2367x; 1.2367x over previous
#include <cuda_runtime.h>
#include <cuda_bf16.h>
#include <math.h>

#define H      1024
#define H2     2048
#define NB     16
#define BEAM   3
#define DEPTH  5
#define MAXN   376            // 1 + 25*5*3
#define BPLEN  8
#define EPSLN  1e-5f
#define UCBC   1.414f
#define NEGINF (-INFINITY)
#define NBLK   296            // 2 CTAs per SM on 148 SMs; whole grid co-resident

// ---------------- persistent device state (no allocs allowed) ----------------
__device__ float g_emb[NB * MAXN * H];        // tree embeddings (~24.6 MB)
__device__ float g_vals[NB * MAXN];
__device__ int   g_visits[NB * MAXN];
__device__ int   g_n[NB];
__device__ int   g_cur[NB];
__device__ int   g_expand[NB];
__device__ float g_X[NB * H];                 // staged cur_emb
__device__ float g_h[NB * BEAM * H2];         // G1 output
__device__ float g_ne[NB * BEAM * H];         // G2 output (candidate children)
__device__ float g_zp[4 * NB * H];            // root GEMM k-split partials
__device__ float g_bestv[NB];
__device__ unsigned int g_bar_cnt;            // zero-init; returns to 0 after each barrier
__device__ unsigned int g_bar_gen;            // monotonically increasing across replays

// ---------------- helpers ----------------
__device__ __forceinline__ float geluf(float x) {
    return 0.5f * x * (1.0f + erff(x * 0.70710678118654752440f));
}
__device__ __forceinline__ float warp_sum(float v) {
    v += __shfl_xor_sync(0xffffffffu, v, 16);
    v += __shfl_xor_sync(0xffffffffu, v, 8);
    v += __shfl_xor_sync(0xffffffffu, v, 4);
    v += __shfl_xor_sync(0xffffffffu, v, 2);
    v += __shfl_xor_sync(0xffffffffu, v, 1);
    return v;
}

// Butterfly multi-value reduction: a[0..31] per lane; on return a[0] at lane l
// equals sum over all lanes of original a[l]. 31 SHFL total (vs 160 naive).
// Step at offset o (current size 2o): keep own half (hi lanes keep upper),
// receive partner's matching half.
__device__ __forceinline__ void bfly_reduce32(float* a, int lane) {
#pragma unroll
    for (int o = 16; o >= 1; o >>= 1) {
        bool hi = (lane & o) != 0;
#pragma unroll
        for (int j = 0; j < o; j++) {
            float keep = hi ? a[j + o] : a[j];
            float send = hi ? a[j] : a[j + o];
            float r = __shfl_xor_sync(0xffffffffu, send, o);
            a[j] = keep + r;
        }
    }
}

// Software grid barrier. Safe because all NBLK blocks are co-resident.
__device__ __forceinline__ void grid_barrier() {
    __threadfence();
    __syncthreads();
    if (threadIdx.x == 0) {
        unsigned int gen = ((volatile unsigned int*)&g_bar_gen)[0];
        unsigned int t = atomicAdd(&g_bar_cnt, 1u);
        if (t == NBLK - 1) {
            atomicExch(&g_bar_cnt, 0u);
            __threadfence();
            atomicExch(&g_bar_gen, gen + 1u);
        } else {
            while (((volatile unsigned int*)&g_bar_gen)[0] == gen) { __nanosleep(32); }
            __threadfence();
        }
    }
    __syncthreads();
}

// ---------------- root: z_partial[kc][b][j] = sum_{k in slice} x[b][k]*Wte[k][j]
__global__ void root1_kernel(const float* __restrict__ p, const float* __restrict__ c,
                             const float* __restrict__ Wte) {
    __shared__ float xs[8 * 512];
    int tid = threadIdx.x;
    int jb = blockIdx.x;      // 0..3
    int bg = blockIdx.y;      // 0..1
    int kc = blockIdx.z;      // 0..3
    for (int i = tid; i < 8 * 512; i += 256) {
        int bl = i >> 9, kk = i & 511;
        int k = kc * 512 + kk;
        int bb = bg * 8 + bl;
        xs[i] = (k < H) ? p[bb * H + k] : c[bb * H + (k - H)];
    }
    __syncthreads();
    int j = jb * 256 + tid;
    float acc[8] = {0.f, 0.f, 0.f, 0.f, 0.f, 0.f, 0.f, 0.f};
    for (int kk = 0; kk < 512; kk++) {
        float w = Wte[(kc * 512 + kk) * H + j];
#pragma unroll
        for (int bl = 0; bl < 8; bl++) acc[bl] += xs[bl * 512 + kk] * w;
    }
#pragma unroll
    for (int bl = 0; bl < 8; bl++) {
        int bb = bg * 8 + bl;
        g_zp[(kc * NB + bb) * H + j] = acc[bl];
    }
}

// ---------------- root: bias+gelu+layernorm, init tree ----------------
__global__ void root2_kernel(const float* __restrict__ bte, const float* __restrict__ gln,
                             const float* __restrict__ bln, const float* __restrict__ wv,
                             const float* __restrict__ bv) {
    int b = blockIdx.x, tid = threadIdx.x;
    int lane = tid & 31, warp = tid >> 5;
    __shared__ float red[8];
    float zv[4];
    float s = 0.f;
#pragma unroll
    for (int q = 0; q < 4; q++) {
        int j = tid + q * 256;
        float z = g_zp[(0 * NB + b) * H + j] + g_zp[(1 * NB + b) * H + j] +
                  g_zp[(2 * NB + b) * H + j] + g_zp[(3 * NB + b) * H + j] + bte[j];
        z = geluf(z);
        zv[q] = z;
        s += z;
    }
    s = warp_sum(s);
    if (lane == 0) red[warp] = s;
    __syncthreads();
    if (tid == 0) {
        float t = 0.f;
#pragma unroll
        for (int w = 0; w < 8; w++) t += red[w];
        red[0] = t;
    }
    __syncthreads();
    float mu = red[0] * (1.0f / H);
    __syncthreads();
    float s2 = 0.f;
#pragma unroll
    for (int q = 0; q < 4; q++) { float d = zv[q] - mu; s2 += d * d; }
    s2 = warp_sum(s2);
    if (lane == 0) red[warp] = s2;
    __syncthreads();
    if (tid == 0) {
        float t = 0.f;
#pragma unroll
        for (int w = 0; w < 8; w++) t += red[w];
        red[0] = t;
    }
    __syncthreads();
    float var = red[0] * (1.0f / H);
    float inv = 1.0f / sqrtf(var + EPSLN);
    __syncthreads();
    float vp = 0.f;
#pragma unroll
    for (int q = 0; q < 4; q++) {
        int j = tid + q * 256;
        float r = gln[j] * (zv[q] - mu) * inv + bln[j];
        g_emb[(b * MAXN + 0) * H + j] = r;
        vp += r * wv[j];
    }
    vp = warp_sum(vp);
    if (lane == 0) red[warp] = vp;
    __syncthreads();
    if (tid == 0) {
        float t = 0.f;
#pragma unroll
        for (int w = 0; w < 8; w++) t += red[w];
        g_vals[b * MAXN + 0] = t + bv[0];
        g_visits[b * MAXN + 0] = 1;
        g_n[b] = 1;
        g_cur[b] = 0;
    }
}

// ---------------- prep for sim0/depth0 ----------------
__global__ void prep_kernel() {
    int b = blockIdx.x, tid = threadIdx.x;
    if (tid == 0) {
        g_cur[b] = 0;
        g_expand[b] = ((g_n[b] - 1) < BEAM) ? 1 : 0;
    }
    __syncthreads();
    for (int k = tid; k < H; k += 128)
        g_X[b * H + k] = g_emb[(b * MAXN + 0) * H + k];
}

// ---------------- G1 phase: h[b][r] = gelu(dot(W1row[r], X[b]) + b1[r]) ----------------
// warp-tile = 4 rows x 16 batches; tile = warp*296 + bid (0..1535 valid)
__device__ __forceinline__ void g1_phase(float4* sx4, const float* __restrict__ W1,
                                         const float* __restrict__ b1) {
    int tid = threadIdx.x;
    const float4* X4 = (const float4*)g_X;
    for (int i = tid; i < NB * 256; i += 256) sx4[i] = X4[i];
    __syncthreads();

    int warp = tid >> 5, lane = tid & 31;
    int tt = warp * NBLK + blockIdx.x;
    if (tt < 1536) {
        int row0 = tt * 4;
        float acc[NB][4];
#pragma unroll
        for (int b = 0; b < NB; b++)
#pragma unroll
            for (int i = 0; i < 4; i++) acc[b][i] = 0.f;

        const float4* W4 = (const float4*)W1;
        const float4* wp = W4 + (size_t)row0 * 256 + lane;
#pragma unroll 2
        for (int t = 0; t < 8; t++) {
            float4 wr[4];
#pragma unroll
            for (int i = 0; i < 4; i++) wr[i] = wp[t * 32 + i * 256];
            int k4 = t * 32 + lane;
#pragma unroll
            for (int b = 0; b < NB; b++) {
                float4 x = sx4[b * 256 + k4];
#pragma unroll
                for (int i = 0; i < 4; i++) {
                    acc[b][i] = fmaf(wr[i].x, x.x, acc[b][i]);
                    acc[b][i] = fmaf(wr[i].y, x.y, acc[b][i]);
                    acc[b][i] = fmaf(wr[i].z, x.z, acc[b][i]);
                    acc[b][i] = fmaf(wr[i].w, x.w, acc[b][i]);
                }
            }
        }
        // Butterfly reductions: group0 = acc[0..7][4] (m=0..31), lane m holds out[m];
        // group1 = acc[8..15][4] (m=32..63).
        float* a0 = &acc[0][0];
        bfly_reduce32(a0, lane);
        {
            int bb = lane >> 2; int r = row0 + (lane & 3);
            g_h[bb * (BEAM * H2) + r] = geluf(a0[0] + b1[r]);
        }
        float* a1 = &acc[8][0];
        bfly_reduce32(a1, lane);
        {
            int bb = 8 + (lane >> 2); int r = row0 + (lane & 3);
            g_h[bb * (BEAM * H2) + r] = geluf(a1[0] + b1[r]);
        }
    }
}

// ---------------- G2 phase: ne[b][r] = X[b][d] + 0.1*(dot(W2row[r], h[b][w]) + b2[r])
// block decomposition: bid = ib + 49*(w + 3*bg), valid bid < 294; blocks 294/295 idle.
// tile = warp*49 + ib (valid < 256); row0 = w*1024 + tile*4. Per-block-constant w
// guarantees the staged smem slab h[b][w][:] matches every warp's dot.
__device__ __forceinline__ void g2_phase(float4* sh4, const float* __restrict__ W2,
                                         const float* __restrict__ b2) {
    int tid = threadIdx.x, bid = blockIdx.x;
    if (bid < 294) {
        int ib  = bid % 49;
        int rem = bid / 49;
        int w   = rem % 3;
        int bg  = rem / 3;
        const float4* Hh4 = (const float4*)g_h;
        for (int i = tid; i < 8 * 512; i += 256) {
            int bl = i >> 9, k4 = i & 511;
            int bb = bg * 8 + bl;
            sh4[i] = Hh4[bb * (BEAM * H2 / 4) + w * 512 + k4];
        }
        __syncthreads();

        int warp = tid >> 5, lane = tid & 31;
        int tile = warp * 49 + ib;
        if (tile < 256) {
            int row0 = w * 1024 + tile * 4;
            float acc[8][4];
#pragma unroll
            for (int b = 0; b < 8; b++)
#pragma unroll
                for (int i = 0; i < 4; i++) acc[b][i] = 0.f;

            const float4* W4 = (const float4*)W2;
            const float4* wp = W4 + (size_t)row0 * 512 + lane;
#pragma unroll 2
            for (int t = 0; t < 16; t++) {
                float4 wr[4];
#pragma unroll
                for (int i = 0; i < 4; i++) wr[i] = wp[t * 32 + i * 512];
                int k4 = t * 32 + lane;
#pragma unroll
                for (int b = 0; b < 8; b++) {
                    float4 x = sh4[b * 512 + k4];
#pragma unroll
                    for (int i = 0; i < 4; i++) {
                        acc[b][i] = fmaf(wr[i].x, x.x, acc[b][i]);
                        acc[b][i] = fmaf(wr[i].y, x.y, acc[b][i]);
                        acc[b][i] = fmaf(wr[i].z, x.z, acc[b][i]);
                        acc[b][i] = fmaf(wr[i].w, x.w, acc[b][i]);
                    }
                }
            }
            // Butterfly reduction: 32 accs, lane m holds out[m] after.
            float* a0 = &acc[0][0];
            bfly_reduce32(a0, lane);
            int bl = lane >> 2;
            int r2 = row0 + (lane & 3);
            int bb = bg * 8 + bl;
            float nv = g_X[bb * H + (r2 & 1023)] + 0.1f * (a0[0] + b2[r2]);
            g_ne[bb * (BEAM * H) + r2] = nv;
        }
    }
}

// ---------------- ctl phase (block b, 256 threads): finalize (sim,d) + prep next ----
__device__ void ctl_phase(int b, int sim, int d, int ns,
                          const float* __restrict__ wv, const float* __restrict__ bv) {
    int tid = threadIdx.x, lane = tid & 31, warp = tid >> 5;
    __shared__ float sv[BEAM];
    __shared__ int st[4];
    if (tid == 0) { st[0] = g_n[b]; st[1] = g_cur[b]; st[2] = g_expand[b]; }
    __syncthreads();
    int n = st[0], cur = st[1], exp = st[2];

    if (exp) {
        if (warp < BEAM) {
            float s = 0.f;
            for (int k = lane; k < H; k += 32)
                s += g_ne[b * (BEAM * H) + warp * H + k] * wv[k];
            s = warp_sum(s);
            if (lane == 0) sv[warp] = s + bv[0];
        }
        __syncthreads();
#pragma unroll
        for (int w = 0; w < BEAM; w++) {
            int idx = n + w;
            if (idx < MAXN) {
                for (int k = tid; k < H; k += 256)
                    g_emb[(b * MAXN + idx) * H + k] = g_ne[b * (BEAM * H) + w * H + k];
            }
        }
        if (tid == 0) {
#pragma unroll
            for (int w = 0; w < BEAM; w++) {
                int idx = n + w;
                if (idx < MAXN) {
                    g_vals[b * MAXN + idx] = sv[w];
                    g_visits[b * MAXN + idx] = 1;
                }
            }
        }
        n += BEAM;
    }
    __syncthreads();
    if (tid == 0) {
        g_n[b] = n;
        if (d < DEPTH - 1) {
            // UCB selection (exact reference semantics incl. heap-index quirk)
            int pv = 0;
#pragma unroll
            for (int i = 0; i < BEAM; i++) {
                int pi = cur * BEAM + i;
                if (pi < n) pv += g_visits[b * MAXN + (pi < MAXN - 1 ? pi : MAXN - 1)];
            }
            float log_pv = logf((float)(pv > 1 ? pv : 1));
            float best = NEGINF; int bi = cur;
#pragma unroll
            for (int ci = 0; ci < BEAM; ci++) {
                int child = cur * BEAM + 1 + ci;
                int safe = child < MAXN - 1 ? child : MAXN - 1;
                int vis = g_visits[b * MAXN + safe];
                float cn = (float)(vis > 1 ? vis : 1);
                float ucb = g_vals[b * MAXN + safe] + UCBC * sqrtf(log_pv / cn);
                if (child >= n) ucb = NEGINF;
                if (ucb > best) { best = ucb; bi = child; }
            }
            g_cur[b] = bi;
        } else {
            // leaf + backprop
            int leaf = cur < n - 1 ? cur : n - 1;
            float lv = g_vals[b * MAXN + leaf];
            int node = leaf;
#pragma unroll
            for (int it = 0; it < BPLEN; it++) {
                if (node > 0) {
                    int pnode = (node - 1) / BEAM;
                    float pc = (float)g_visits[b * MAXN + pnode];
                    g_vals[b * MAXN + pnode] =
                        (g_vals[b * MAXN + pnode] * pc + lv) / (pc + 1.0f);
                    g_visits[b * MAXN + pnode] += 1;
                    node = pnode;
                }
            }
            g_visits[b * MAXN + leaf] += 1;
        }
    }
    __syncthreads();

    // prep next step
    int sim_p = (d < DEPTH - 1) ? sim : sim + 1;
    int d_p   = (d < DEPTH - 1) ? d + 1 : 0;
    if (sim_p >= ns) {
        if (tid == 0) g_expand[b] = 0;
    } else {
        if (tid == 0) {
            int cp = (d_p == 0) ? 0 : g_cur[b];
            g_cur[b] = cp;
            int np = g_n[b];
            g_expand[b] = ((np - 1) < (cp + 1) * BEAM) ? 1 : 0;
            st[3] = cp;
        }
        __syncthreads();
        int cp = st[3];
        for (int k = tid; k < H; k += 256)
            g_X[b * H + k] = g_emb[(b * MAXN + cp) * H + k];
    }
}

// ---------------- persistent main loop: 125 steps, grid barriers between phases ----
__global__ void __launch_bounds__(256, 2)
main_kernel(const float* __restrict__ W1, const float* __restrict__ b1,
            const float* __restrict__ W2, const float* __restrict__ b2,
            const float* __restrict__ wv, const float* __restrict__ bv,
            const int* __restrict__ nsp) {
    extern __shared__ float4 smem4[];   // 64KB, reused by g1 (X slab) and g2 (h slab)
    __shared__ int s_any;
    int tid = threadIdx.x;
    int bid = blockIdx.x;
    int ns = nsp[0];

    for (int sim = 0; sim < ns; sim++) {
        for (int d = 0; d < DEPTH; d++) {
            // grid-uniform gate: g_expand written before the preceding barrier.
            if (tid == 0) {
                int a = 0;
#pragma unroll
                for (int b = 0; b < NB; b++) a |= g_expand[b];
                s_any = a;
            }
            __syncthreads();
            int any = s_any;
            __syncthreads();

            if (any) {
                g1_phase(smem4, W1, b1);
                grid_barrier();
                g2_phase(smem4, W2, b2);
                grid_barrier();
            }
            if (bid < NB) ctl_phase(bid, sim, d, ns, wv, bv);
            grid_barrier();
        }
    }
}

// ---------------- final: per-batch argmax (first-max) + copy emb ----------------
__global__ void final1_kernel(float* __restrict__ out) {
    int b = blockIdx.x, tid = threadIdx.x;
    int lane = tid & 31, warp = tid >> 5;
    __shared__ float wmax[8];
    __shared__ int s_bi;
    int n = g_n[b];
    float mx = NEGINF;
    for (int i = tid; i < n; i += 256) mx = fmaxf(mx, g_vals[b * MAXN + i]);
#pragma unroll
    for (int off = 16; off > 0; off >>= 1)
        mx = fmaxf(mx, __shfl_xor_sync(0xffffffffu, mx, off));
    if (lane == 0) wmax[warp] = mx;
    __syncthreads();
    if (tid == 0) {
        float m = wmax[0];
#pragma unroll
        for (int w = 1; w < 8; w++) m = fmaxf(m, wmax[w]);
        wmax[0] = m;
        s_bi = 0x7fffffff;
    }
    __syncthreads();
    float M = wmax[0];
    for (int i = tid; i < n; i += 256)
        if (g_vals[b * MAXN + i] == M) atomicMin(&s_bi, i);
    __syncthreads();
    int bi = s_bi;
    for (int k = tid; k < H; k += 256)
        out[b * H + k] = g_emb[(b * MAXN + bi) * H + k];
    if (tid == 0) g_bestv[b] = M;
}

__global__ void final2_kernel(float* __restrict__ out) {
    int lane = threadIdx.x;
    float v = (lane < NB) ? g_bestv[lane] : NEGINF;
    float m = v;
#pragma unroll
    for (int off = 16; off > 0; off >>= 1)
        m = fmaxf(m, __shfl_xor_sync(0xffffffffu, m, off));
    if (lane < NB) {
        float conf = fminf(v / (m + 1e-8f), 1.0f);
        out[NB * H + lane] = conf;          // confidence [16]
        out[NB * H + NB + lane] = v;        // best_vals  [16]
    }
}

// ---------------- launch ----------------
extern "C" void kernel_launch(void* const* d_in, const int* in_sizes, int n_in,
                              void* d_out, int out_size) {
    const float* p   = (const float*)d_in[0];
    const float* c   = (const float*)d_in[1];
    const float* Wte = (const float*)d_in[2];
    const float* bte = (const float*)d_in[3];
    const float* gln = (const float*)d_in[4];
    const float* bln = (const float*)d_in[5];
    const float* wv  = (const float*)d_in[6];
    const float* bv  = (const float*)d_in[7];
    const float* W1  = (const float*)d_in[8];
    const float* b1  = (const float*)d_in[9];
    const float* W2  = (const float*)d_in[10];
    const float* b2  = (const float*)d_in[11];
    const int*   nsp = (const int*)d_in[12];
    float* out = (float*)d_out;

    cudaFuncSetAttribute(main_kernel, cudaFuncAttributeMaxDynamicSharedMemorySize, 65536);

    root1_kernel<<<dim3(4, 2, 4), 256>>>(p, c, Wte);
    root2_kernel<<<NB, 256>>>(bte, gln, bln, wv, bv);
    prep_kernel<<<NB, 128>>>();
    main_kernel<<<NBLK, 256, 65536>>>(W1, b1, W2, b2, wv, bv, nsp);
    final1_kernel<<<NB, 256>>>(out);
    final2_kernel<<<1, 32>>>(out);
}